// round 12
// baseline (speedup 1.0000x reference)
#include <cuda_runtime.h>
#include <cuda_bf16.h>
#include <cstdint>

#define NMAX 1000000
#define NBUCKETS 65536            // key bits 31..46
#define CAP 128                   // slab capacity (lambda ~30; >>10 sigma safe)
#define WPB 8                     // warps (=buckets) per block in rankmap
#define NTILES (NBUCKETS / WPB)   // 8192 blocks

// ---------------------------------------------------------------------------
// Static device scratch (no allocations allowed anywhere)
// ---------------------------------------------------------------------------
__device__ ulonglong2 g_bpairs[(size_t)NBUCKETS * CAP]; // slab: {key, idx}
__device__ uint32_t   g_hist[NBUCKETS];       // zero-init; reset by rankmap
__device__ unsigned long long g_tilestate[NTILES]; // lookback state; reset by decode

#define KEYMASK ((1ull << 47) - 1ull)
#define FIRSTBIT (1ull << 63)

// ---------------------------------------------------------------------------
// Packed f32x2 helpers (FFMA2 — PTX-only on sm_103a)
// ---------------------------------------------------------------------------
__device__ __forceinline__ void fma2(uint64_t& d, uint64_t a, uint64_t b, uint64_t c) {
    asm("fma.rn.f32x2 %0, %1, %2, %3;" : "=l"(d) : "l"(a), "l"(b), "l"(c));
}
__device__ __forceinline__ uint64_t dup2(float x) {
    uint64_t r; uint32_t u = __float_as_uint(x);
    asm("mov.b64 %0, {%1, %1};" : "=l"(r) : "r"(u));
    return r;
}
__device__ __forceinline__ uint64_t pack2(float lo, float hi) {
    uint64_t r;
    asm("mov.b64 %0, {%1, %2};" : "=l"(r) : "r"(__float_as_uint(lo)), "r"(__float_as_uint(hi)));
    return r;
}
__device__ __forceinline__ void unpack2(uint64_t v, float& lo, float& hi) {
    uint32_t a, b;
    asm("mov.b64 {%0, %1}, %2;" : "=r"(a), "=r"(b) : "l"(v));
    lo = __uint_as_float(a); hi = __uint_as_float(b);
}

// ---------------------------------------------------------------------------
// Kernel 1: MLP decode, TWO points per thread. Epilogue: key + slab write +
// out_coords zeroing + tile-state reset.
// ---------------------------------------------------------------------------
__global__ void __launch_bounds__(256)
decode_kernel(const float* __restrict__ feats,
              const int*   __restrict__ coords,
              const int*   __restrict__ mask,
              const float* __restrict__ W1, const float* __restrict__ b1,
              const float* __restrict__ W2, const float* __restrict__ b2,
              const float* __restrict__ W3, const float* __restrict__ b3,
              float* __restrict__ out, int n)
{
    __shared__ __align__(16) float sW1[64 * 32];
    __shared__ __align__(16) float sW2[32 * 16];
    __shared__ __align__(16) float sW3[16 * 3];
    __shared__ __align__(16) float sb1[32];
    __shared__ __align__(16) float sb2[16];
    __shared__ __align__(16) float sb3[4];

    for (int t = threadIdx.x; t < 64 * 32; t += blockDim.x) sW1[t] = W1[t];
    for (int t = threadIdx.x; t < 32 * 16; t += blockDim.x) sW2[t] = W2[t];
    for (int t = threadIdx.x; t < 16 * 3;  t += blockDim.x) sW3[t] = W3[t];
    if (threadIdx.x < 32) sb1[threadIdx.x] = b1[threadIdx.x];
    if (threadIdx.x < 16) sb2[threadIdx.x] = b2[threadIdx.x];
    if (threadIdx.x < 3)  sb3[threadIdx.x] = b3[threadIdx.x];
    __syncthreads();

    int nhalf = (n + 1) >> 1;
    int i = blockIdx.x * blockDim.x + threadIdx.x;

    // reset lookback tile state for the next rankmap launch
    if (i < NTILES) g_tilestate[i] = 0ull;

    if (i >= nhalf) return;
    int iA = i;
    int iB = i + nhalf;
    bool hasB = (iB < n);
    int iBs = hasB ? iB : iA;            // safe source for B-lane loads

    // zero out_coords rows (rows < total get overwritten by rankmap firsts)
    float4* ocz = reinterpret_cast<float4*>(out + (size_t)3 * n);
    ocz[iA] = make_float4(0.f, 0.f, 0.f, 0.f);
    if (hasB) ocz[iB] = make_float4(0.f, 0.f, 0.f, 0.f);

    // ---- layer 1: 64 -> 32, two points, shared weight loads ----
    uint64_t accA[16], accB[16];
#pragma unroll
    for (int p = 0; p < 16; p++) {
        uint64_t b = pack2(sb1[2 * p], sb1[2 * p + 1]);
        accA[p] = b; accB[p] = b;
    }

    const ulonglong2* w1q = reinterpret_cast<const ulonglong2*>(sW1); // [64][8]
    const float4* fA = reinterpret_cast<const float4*>(feats) + (size_t)iA * 16;
    const float4* fB = reinterpret_cast<const float4*>(feats) + (size_t)iBs * 16;
#pragma unroll
    for (int k4 = 0; k4 < 16; k4++) {
        float4 fa = fA[k4];
        float4 fb = fB[k4];
        uint64_t a0 = dup2(fa.x), a1 = dup2(fa.y), a2 = dup2(fa.z), a3 = dup2(fa.w);
        uint64_t e0 = dup2(fb.x), e1 = dup2(fb.y), e2 = dup2(fb.z), e3 = dup2(fb.w);
        const ulonglong2* r0 = &w1q[(k4 * 4 + 0) * 8];
        const ulonglong2* r1 = &w1q[(k4 * 4 + 1) * 8];
        const ulonglong2* r2 = &w1q[(k4 * 4 + 2) * 8];
        const ulonglong2* r3 = &w1q[(k4 * 4 + 3) * 8];
#pragma unroll
        for (int q = 0; q < 8; q++) {
            ulonglong2 w;
            w = r0[q];
            fma2(accA[2*q], a0, w.x, accA[2*q]); fma2(accA[2*q+1], a0, w.y, accA[2*q+1]);
            fma2(accB[2*q], e0, w.x, accB[2*q]); fma2(accB[2*q+1], e0, w.y, accB[2*q+1]);
            w = r1[q];
            fma2(accA[2*q], a1, w.x, accA[2*q]); fma2(accA[2*q+1], a1, w.y, accA[2*q+1]);
            fma2(accB[2*q], e1, w.x, accB[2*q]); fma2(accB[2*q+1], e1, w.y, accB[2*q+1]);
            w = r2[q];
            fma2(accA[2*q], a2, w.x, accA[2*q]); fma2(accA[2*q+1], a2, w.y, accA[2*q+1]);
            fma2(accB[2*q], e2, w.x, accB[2*q]); fma2(accB[2*q+1], e2, w.y, accB[2*q+1]);
            w = r3[q];
            fma2(accA[2*q], a3, w.x, accA[2*q]); fma2(accA[2*q+1], a3, w.y, accA[2*q+1]);
            fma2(accB[2*q], e3, w.x, accB[2*q]); fma2(accB[2*q+1], e3, w.y, accB[2*q+1]);
        }
    }

    float h1A[32], h1B[32];
#pragma unroll
    for (int p = 0; p < 16; p++) {
        float lo, hi;
        unpack2(accA[p], lo, hi);
        h1A[2*p] = fmaxf(lo, 0.0f); h1A[2*p+1] = fmaxf(hi, 0.0f);
        unpack2(accB[p], lo, hi);
        h1B[2*p] = fmaxf(lo, 0.0f); h1B[2*p+1] = fmaxf(hi, 0.0f);
    }

    // ---- layer 2: 32 -> 16, two points, shared weight loads ----
    uint64_t ac2A[8], ac2B[8];
#pragma unroll
    for (int p = 0; p < 8; p++) {
        uint64_t b = pack2(sb2[2 * p], sb2[2 * p + 1]);
        ac2A[p] = b; ac2B[p] = b;
    }
    const ulonglong2* w2q = reinterpret_cast<const ulonglong2*>(sW2); // [32][4]
#pragma unroll
    for (int k = 0; k < 32; k++) {
        uint64_t a = dup2(h1A[k]);
        uint64_t e = dup2(h1B[k]);
        const ulonglong2* wr = &w2q[k * 4];
#pragma unroll
        for (int q = 0; q < 4; q++) {
            ulonglong2 w = wr[q];
            fma2(ac2A[2*q],   a, w.x, ac2A[2*q]);   fma2(ac2A[2*q+1], a, w.y, ac2A[2*q+1]);
            fma2(ac2B[2*q],   e, w.x, ac2B[2*q]);   fma2(ac2B[2*q+1], e, w.y, ac2B[2*q+1]);
        }
    }

    float h2A[16], h2B[16];
#pragma unroll
    for (int p = 0; p < 8; p++) {
        float lo, hi;
        unpack2(ac2A[p], lo, hi);
        h2A[2*p] = fmaxf(lo, 0.0f); h2A[2*p+1] = fmaxf(hi, 0.0f);
        unpack2(ac2B[p], lo, hi);
        h2B[2*p] = fmaxf(lo, 0.0f); h2B[2*p+1] = fmaxf(hi, 0.0f);
    }

    // ---- layer 3: 16 -> 3, two points ----
    float oA0 = sb3[0], oA1 = sb3[1], oA2 = sb3[2];
    float oB0 = sb3[0], oB1 = sb3[1], oB2 = sb3[2];
#pragma unroll
    for (int k = 0; k < 16; k++) {
        float w0 = sW3[k * 3 + 0], w1 = sW3[k * 3 + 1], w2 = sW3[k * 3 + 2];
        oA0 = fmaf(h2A[k], w0, oA0); oA1 = fmaf(h2A[k], w1, oA1); oA2 = fmaf(h2A[k], w2, oA2);
        oB0 = fmaf(h2B[k], w0, oB0); oB1 = fmaf(h2B[k], w1, oB1); oB2 = fmaf(h2B[k], w2, oB2);
    }

    // ---- epilogue per point: direct slab write ----
    {
        float m = (mask[iA] != 0) ? 1.0f : 0.0f;
        float o0 = oA0 * m, o1 = oA1 * m, o2 = oA2 * m;
        out[(size_t)3 * iA + 0] = o0;
        out[(size_t)3 * iA + 1] = o1;
        out[(size_t)3 * iA + 2] = o2;
        int4 c = reinterpret_cast<const int4*>(coords)[iA];
        int n1 = c.y + (int)rintf(o0);
        int n2 = c.z + (int)rintf(o1);
        int n3 = c.w + (int)rintf(o2);
        uint64_t key = ((uint64_t)(uint32_t)c.x         << 36)
                     | ((uint64_t)(uint32_t)(n1 + 1024) << 24)
                     | ((uint64_t)(uint32_t)(n2 + 1024) << 12)
                     |  (uint64_t)(uint32_t)(n3 + 1024);
        uint32_t b = (uint32_t)(key >> 31);
        uint32_t lidx = atomicAdd(&g_hist[b], 1u);
        if (lidx < CAP) {
            ulonglong2 pr; pr.x = key; pr.y = (uint64_t)(uint32_t)iA;
            g_bpairs[(size_t)b * CAP + lidx] = pr;
        }
    }
    if (hasB) {
        float m = (mask[iB] != 0) ? 1.0f : 0.0f;
        float o0 = oB0 * m, o1 = oB1 * m, o2 = oB2 * m;
        out[(size_t)3 * iB + 0] = o0;
        out[(size_t)3 * iB + 1] = o1;
        out[(size_t)3 * iB + 2] = o2;
        int4 c = reinterpret_cast<const int4*>(coords)[iB];
        int n1 = c.y + (int)rintf(o0);
        int n2 = c.z + (int)rintf(o1);
        int n3 = c.w + (int)rintf(o2);
        uint64_t key = ((uint64_t)(uint32_t)c.x         << 36)
                     | ((uint64_t)(uint32_t)(n1 + 1024) << 24)
                     | ((uint64_t)(uint32_t)(n2 + 1024) << 12)
                     |  (uint64_t)(uint32_t)(n3 + 1024);
        uint32_t b = (uint32_t)(key >> 31);
        uint32_t lidx = atomicAdd(&g_hist[b], 1u);
        if (lidx < CAP) {
            ulonglong2 pr; pr.x = key; pr.y = (uint64_t)(uint32_t)iB;
            g_bpairs[(size_t)b * CAP + lidx] = pr;
        }
    }
}

// ---------------------------------------------------------------------------
// Kernel 2: fused rank + scan (decoupled lookback) + map.
// Block = 8 warps = 8 buckets. One kernel, one slab read, all outputs.
// ---------------------------------------------------------------------------
__global__ void __launch_bounds__(WPB * 32)
rankmap_kernel(float* __restrict__ out, int n)
{
    __shared__ uint64_t sk[WPB][CAP];   // bit63 = first flag after pass 1
    __shared__ uint32_t sv[WPB][CAP];
    __shared__ uint32_t s_uniq[WPB];    // per-warp unique counts
    __shared__ uint32_t s_wbase[WPB];   // per-warp global rank base

    int warp = threadIdx.x >> 5;
    int lane = threadIdx.x & 31;
    int bid = blockIdx.x;
    int b = bid * WPB + warp;

    uint32_t raw = g_hist[b];
    int cnt = (int)(raw < CAP ? raw : CAP);
    if (lane == 0) g_hist[b] = 0u;       // reset for next graph replay

    uint64_t* k = sk[warp];
    uint32_t* v = sv[warp];
    for (int p = lane; p < cnt; p += 32) {
        ulonglong2 pr = g_bpairs[(size_t)b * CAP + p];
        k[p] = pr.x;
        v[p] = (uint32_t)pr.y;
    }
    __syncwarp();

    // pass 1: first-occurrence flags -> bit 63 in smem; count uniques
    uint32_t u = 0;
    for (int p = lane; p < cnt; p += 32) {
        uint64_t key = k[p];
        bool first = true;
        for (int j = 0; j < p; j++)
            if ((k[j] & KEYMASK) == key) { first = false; break; }
        u += first ? 1u : 0u;
        if (first) k[p] = key | FIRSTBIT;   // lanes own disjoint p: no race
    }
#pragma unroll
    for (int d = 16; d > 0; d >>= 1)
        u += __shfl_xor_sync(0xFFFFFFFFu, u, d);
    if (lane == 0) s_uniq[warp] = u;
    __syncthreads();

    // ---- warp 0: block aggregate + decoupled lookback scan ----
    if (warp == 0) {
        uint32_t mine = (lane < WPB) ? s_uniq[lane] : 0u;
        // inclusive scan over the 8 values (within first 8 lanes)
        uint32_t pre = mine;
#pragma unroll
        for (int d = 1; d < WPB; d <<= 1) {
            uint32_t t = __shfl_up_sync(0xFFFFFFFFu, pre, d);
            if (lane >= d) pre += t;
        }
        uint32_t agg = __shfl_sync(0xFFFFFFFFu, pre, WPB - 1);

        // publish partial (or inclusive for tile 0)
        if (lane == 0) {
            unsigned long long packed = bid == 0
                ? (((unsigned long long)agg << 2) | 2ull)
                : (((unsigned long long)agg << 2) | 1ull);
            atomicExch(&g_tilestate[bid], packed);
        }

        uint32_t excl = 0;
        if (bid > 0) {
            int hib = bid;                      // window is [hib-32, hib)
            while (true) {
                int j = hib - 32 + (int)lane;
                unsigned long long st = 0ull;
                bool valid = (j >= 0);
                if (valid)
                    st = *((volatile unsigned long long*)&g_tilestate[j]);
                uint32_t flag = (uint32_t)(st & 3ull);
                unsigned inc = __ballot_sync(0xFFFFFFFFu, valid && flag == 2u);
                unsigned zer = __ballot_sync(0xFFFFFFFFu, valid && flag == 0u);
                if (inc) {
                    int hi = 31 - __clz(inc);
                    unsigned above = (hi == 31) ? 0u : (~0u << (hi + 1));
                    if (zer & above) continue;      // unready above; retry
                    uint32_t val = (valid && lane >= (uint32_t)hi)
                                 ? (uint32_t)(st >> 2) : 0u;
#pragma unroll
                    for (int d = 16; d > 0; d >>= 1)
                        val += __shfl_xor_sync(0xFFFFFFFFu, val, d);
                    excl += val;
                    break;
                } else {
                    if (zer) continue;              // retry window
                    uint32_t val = valid ? (uint32_t)(st >> 2) : 0u;
#pragma unroll
                    for (int d = 16; d > 0; d >>= 1)
                        val += __shfl_xor_sync(0xFFFFFFFFu, val, d);
                    excl += val;
                    hib -= 32;                      // move window down
                }
            }
            // publish inclusive
            if (lane == 0)
                atomicExch(&g_tilestate[bid],
                           ((unsigned long long)(excl + agg) << 2) | 2ull);
        }

        // per-warp global bases: excl + exclusive-prefix within block
        if (lane < WPB) s_wbase[lane] = excl + pre - mine;
    }
    __syncthreads();

    if (cnt == 0) return;
    uint32_t base = s_wbase[warp];

    // pass 2 + map: local rank among distinct, inv write, out_coords write
    for (int p = lane; p < cnt; p += 32) {
        uint64_t kp = k[p];
        uint64_t myk = kp & KEYMASK;
        uint32_t less = 0;
        for (int j = 0; j < cnt; j++) {
            uint64_t kj = k[j];
            less += (uint32_t)(((kj & KEYMASK) < myk) & (kj >> 63));
        }
        uint32_t r = base + less;

        // inv map (float32) at offset 7n
        out[(size_t)7 * n + v[p]] = (float)r;

        if (kp & FIRSTBIT) {
            // equal keys => identical new_coords; mean == the coords
            float cx = (float)(int)((kp >> 36) & 0x7FFu);
            float c1 = (float)((int)((kp >> 24) & 0xFFFu) - 1024);
            float c2 = (float)((int)((kp >> 12) & 0xFFFu) - 1024);
            float c3 = (float)((int)( kp        & 0xFFFu) - 1024);
            reinterpret_cast<float4*>(out + (size_t)3 * n)[r] =
                make_float4(cx, c1, c2, c3);
        }
    }
}

// ---------------------------------------------------------------------------
// Host launch — TWO kernels total
// ---------------------------------------------------------------------------
extern "C" void kernel_launch(void* const* d_in, const int* in_sizes, int n_in,
                              void* d_out, int out_size)
{
    const float* feats  = (const float*)d_in[0];
    const int*   coords = (const int*)d_in[1];
    const int*   mask   = (const int*)d_in[2];
    const float* W1 = (const float*)d_in[3];
    const float* b1 = (const float*)d_in[4];
    const float* W2 = (const float*)d_in[5];
    const float* b2 = (const float*)d_in[6];
    const float* W3 = (const float*)d_in[7];
    const float* b3 = (const float*)d_in[8];
    float* out = (float*)d_out;

    int n = in_sizes[0] / 64;
    if (n > NMAX) n = NMAX;

    const int BLK = 256;
    int nhalf = (n + 1) >> 1;
    int gridD = (nhalf + BLK - 1) / BLK;

    // 1) decode (2 pts/thread) + keys + slab write + zero tail + state reset
    decode_kernel<<<gridD, BLK>>>(feats, coords, mask, W1, b1, W2, b2, W3, b3, out, n);

    // 2) fused rank + single-pass scan + map
    rankmap_kernel<<<NTILES, WPB * 32>>>(out, n);
}

// round 13
// speedup vs baseline: 1.0945x; 1.0945x over previous
#include <cuda_runtime.h>
#include <cuda_bf16.h>
#include <cstdint>

#define NMAX 1000000
#define NBUCKETS 65536            // key bits 31..46
#define CAP 128                   // slab capacity (lambda ~30; >>10 sigma safe)
#define WPB 8                     // warps per block in rankmap
#define BPW 8                     // buckets per warp (sequential)
#define NT2 (NBUCKETS / (WPB * BPW))   // 1024 tiles -> shallow lookback chain

// ---------------------------------------------------------------------------
// Static device scratch (no allocations allowed anywhere)
// ---------------------------------------------------------------------------
__device__ ulonglong2 g_bpairs[(size_t)NBUCKETS * CAP]; // slab: {key, idx}
__device__ uint32_t   g_hist[NBUCKETS];       // zero-init; reset by rankmap
__device__ unsigned long long g_tilestate[NT2]; // lookback state; reset by decode

#define KEYMASK ((1ull << 47) - 1ull)
#define FIRSTBIT (1ull << 63)

// ---------------------------------------------------------------------------
// Packed f32x2 helpers (FFMA2 — PTX-only on sm_103a)
// ---------------------------------------------------------------------------
__device__ __forceinline__ void fma2(uint64_t& d, uint64_t a, uint64_t b, uint64_t c) {
    asm("fma.rn.f32x2 %0, %1, %2, %3;" : "=l"(d) : "l"(a), "l"(b), "l"(c));
}
__device__ __forceinline__ uint64_t dup2(float x) {
    uint64_t r; uint32_t u = __float_as_uint(x);
    asm("mov.b64 %0, {%1, %1};" : "=l"(r) : "r"(u));
    return r;
}
__device__ __forceinline__ uint64_t pack2(float lo, float hi) {
    uint64_t r;
    asm("mov.b64 %0, {%1, %2};" : "=l"(r) : "r"(__float_as_uint(lo)), "r"(__float_as_uint(hi)));
    return r;
}
__device__ __forceinline__ void unpack2(uint64_t v, float& lo, float& hi) {
    uint32_t a, b;
    asm("mov.b64 {%0, %1}, %2;" : "=r"(a), "=r"(b) : "l"(v));
    lo = __uint_as_float(a); hi = __uint_as_float(b);
}

// ---------------------------------------------------------------------------
// Kernel 1: MLP decode, TWO points per thread. Epilogue: key + slab write +
// out_coords zeroing + tile-state reset.
// ---------------------------------------------------------------------------
__global__ void __launch_bounds__(256)
decode_kernel(const float* __restrict__ feats,
              const int*   __restrict__ coords,
              const int*   __restrict__ mask,
              const float* __restrict__ W1, const float* __restrict__ b1,
              const float* __restrict__ W2, const float* __restrict__ b2,
              const float* __restrict__ W3, const float* __restrict__ b3,
              float* __restrict__ out, int n)
{
    __shared__ __align__(16) float sW1[64 * 32];
    __shared__ __align__(16) float sW2[32 * 16];
    __shared__ __align__(16) float sW3[16 * 3];
    __shared__ __align__(16) float sb1[32];
    __shared__ __align__(16) float sb2[16];
    __shared__ __align__(16) float sb3[4];

    for (int t = threadIdx.x; t < 64 * 32; t += blockDim.x) sW1[t] = W1[t];
    for (int t = threadIdx.x; t < 32 * 16; t += blockDim.x) sW2[t] = W2[t];
    for (int t = threadIdx.x; t < 16 * 3;  t += blockDim.x) sW3[t] = W3[t];
    if (threadIdx.x < 32) sb1[threadIdx.x] = b1[threadIdx.x];
    if (threadIdx.x < 16) sb2[threadIdx.x] = b2[threadIdx.x];
    if (threadIdx.x < 3)  sb3[threadIdx.x] = b3[threadIdx.x];
    __syncthreads();

    int nhalf = (n + 1) >> 1;
    int i = blockIdx.x * blockDim.x + threadIdx.x;

    // reset lookback tile state for the next rankmap launch
    if (i < NT2) g_tilestate[i] = 0ull;

    if (i >= nhalf) return;
    int iA = i;
    int iB = i + nhalf;
    bool hasB = (iB < n);
    int iBs = hasB ? iB : iA;            // safe source for B-lane loads

    // zero out_coords rows (rows < total get overwritten by rankmap firsts)
    float4* ocz = reinterpret_cast<float4*>(out + (size_t)3 * n);
    ocz[iA] = make_float4(0.f, 0.f, 0.f, 0.f);
    if (hasB) ocz[iB] = make_float4(0.f, 0.f, 0.f, 0.f);

    // ---- layer 1: 64 -> 32, two points, shared weight loads ----
    uint64_t accA[16], accB[16];
#pragma unroll
    for (int p = 0; p < 16; p++) {
        uint64_t b = pack2(sb1[2 * p], sb1[2 * p + 1]);
        accA[p] = b; accB[p] = b;
    }

    const ulonglong2* w1q = reinterpret_cast<const ulonglong2*>(sW1); // [64][8]
    const float4* fA = reinterpret_cast<const float4*>(feats) + (size_t)iA * 16;
    const float4* fB = reinterpret_cast<const float4*>(feats) + (size_t)iBs * 16;
#pragma unroll
    for (int k4 = 0; k4 < 16; k4++) {
        float4 fa = fA[k4];
        float4 fb = fB[k4];
        uint64_t a0 = dup2(fa.x), a1 = dup2(fa.y), a2 = dup2(fa.z), a3 = dup2(fa.w);
        uint64_t e0 = dup2(fb.x), e1 = dup2(fb.y), e2 = dup2(fb.z), e3 = dup2(fb.w);
        const ulonglong2* r0 = &w1q[(k4 * 4 + 0) * 8];
        const ulonglong2* r1 = &w1q[(k4 * 4 + 1) * 8];
        const ulonglong2* r2 = &w1q[(k4 * 4 + 2) * 8];
        const ulonglong2* r3 = &w1q[(k4 * 4 + 3) * 8];
#pragma unroll
        for (int q = 0; q < 8; q++) {
            ulonglong2 w;
            w = r0[q];
            fma2(accA[2*q], a0, w.x, accA[2*q]); fma2(accA[2*q+1], a0, w.y, accA[2*q+1]);
            fma2(accB[2*q], e0, w.x, accB[2*q]); fma2(accB[2*q+1], e0, w.y, accB[2*q+1]);
            w = r1[q];
            fma2(accA[2*q], a1, w.x, accA[2*q]); fma2(accA[2*q+1], a1, w.y, accA[2*q+1]);
            fma2(accB[2*q], e1, w.x, accB[2*q]); fma2(accB[2*q+1], e1, w.y, accB[2*q+1]);
            w = r2[q];
            fma2(accA[2*q], a2, w.x, accA[2*q]); fma2(accA[2*q+1], a2, w.y, accA[2*q+1]);
            fma2(accB[2*q], e2, w.x, accB[2*q]); fma2(accB[2*q+1], e2, w.y, accB[2*q+1]);
            w = r3[q];
            fma2(accA[2*q], a3, w.x, accA[2*q]); fma2(accA[2*q+1], a3, w.y, accA[2*q+1]);
            fma2(accB[2*q], e3, w.x, accB[2*q]); fma2(accB[2*q+1], e3, w.y, accB[2*q+1]);
        }
    }

    float h1A[32], h1B[32];
#pragma unroll
    for (int p = 0; p < 16; p++) {
        float lo, hi;
        unpack2(accA[p], lo, hi);
        h1A[2*p] = fmaxf(lo, 0.0f); h1A[2*p+1] = fmaxf(hi, 0.0f);
        unpack2(accB[p], lo, hi);
        h1B[2*p] = fmaxf(lo, 0.0f); h1B[2*p+1] = fmaxf(hi, 0.0f);
    }

    // ---- layer 2: 32 -> 16, two points, shared weight loads ----
    uint64_t ac2A[8], ac2B[8];
#pragma unroll
    for (int p = 0; p < 8; p++) {
        uint64_t b = pack2(sb2[2 * p], sb2[2 * p + 1]);
        ac2A[p] = b; ac2B[p] = b;
    }
    const ulonglong2* w2q = reinterpret_cast<const ulonglong2*>(sW2); // [32][4]
#pragma unroll
    for (int k = 0; k < 32; k++) {
        uint64_t a = dup2(h1A[k]);
        uint64_t e = dup2(h1B[k]);
        const ulonglong2* wr = &w2q[k * 4];
#pragma unroll
        for (int q = 0; q < 4; q++) {
            ulonglong2 w = wr[q];
            fma2(ac2A[2*q],   a, w.x, ac2A[2*q]);   fma2(ac2A[2*q+1], a, w.y, ac2A[2*q+1]);
            fma2(ac2B[2*q],   e, w.x, ac2B[2*q]);   fma2(ac2B[2*q+1], e, w.y, ac2B[2*q+1]);
        }
    }

    float h2A[16], h2B[16];
#pragma unroll
    for (int p = 0; p < 8; p++) {
        float lo, hi;
        unpack2(ac2A[p], lo, hi);
        h2A[2*p] = fmaxf(lo, 0.0f); h2A[2*p+1] = fmaxf(hi, 0.0f);
        unpack2(ac2B[p], lo, hi);
        h2B[2*p] = fmaxf(lo, 0.0f); h2B[2*p+1] = fmaxf(hi, 0.0f);
    }

    // ---- layer 3: 16 -> 3, two points ----
    float oA0 = sb3[0], oA1 = sb3[1], oA2 = sb3[2];
    float oB0 = sb3[0], oB1 = sb3[1], oB2 = sb3[2];
#pragma unroll
    for (int k = 0; k < 16; k++) {
        float w0 = sW3[k * 3 + 0], w1 = sW3[k * 3 + 1], w2 = sW3[k * 3 + 2];
        oA0 = fmaf(h2A[k], w0, oA0); oA1 = fmaf(h2A[k], w1, oA1); oA2 = fmaf(h2A[k], w2, oA2);
        oB0 = fmaf(h2B[k], w0, oB0); oB1 = fmaf(h2B[k], w1, oB1); oB2 = fmaf(h2B[k], w2, oB2);
    }

    // ---- epilogue per point: direct slab write ----
    {
        float m = (mask[iA] != 0) ? 1.0f : 0.0f;
        float o0 = oA0 * m, o1 = oA1 * m, o2 = oA2 * m;
        out[(size_t)3 * iA + 0] = o0;
        out[(size_t)3 * iA + 1] = o1;
        out[(size_t)3 * iA + 2] = o2;
        int4 c = reinterpret_cast<const int4*>(coords)[iA];
        int n1 = c.y + (int)rintf(o0);
        int n2 = c.z + (int)rintf(o1);
        int n3 = c.w + (int)rintf(o2);
        uint64_t key = ((uint64_t)(uint32_t)c.x         << 36)
                     | ((uint64_t)(uint32_t)(n1 + 1024) << 24)
                     | ((uint64_t)(uint32_t)(n2 + 1024) << 12)
                     |  (uint64_t)(uint32_t)(n3 + 1024);
        uint32_t b = (uint32_t)(key >> 31);
        uint32_t lidx = atomicAdd(&g_hist[b], 1u);
        if (lidx < CAP) {
            ulonglong2 pr; pr.x = key; pr.y = (uint64_t)(uint32_t)iA;
            g_bpairs[(size_t)b * CAP + lidx] = pr;
        }
    }
    if (hasB) {
        float m = (mask[iB] != 0) ? 1.0f : 0.0f;
        float o0 = oB0 * m, o1 = oB1 * m, o2 = oB2 * m;
        out[(size_t)3 * iB + 0] = o0;
        out[(size_t)3 * iB + 1] = o1;
        out[(size_t)3 * iB + 2] = o2;
        int4 c = reinterpret_cast<const int4*>(coords)[iB];
        int n1 = c.y + (int)rintf(o0);
        int n2 = c.z + (int)rintf(o1);
        int n3 = c.w + (int)rintf(o2);
        uint64_t key = ((uint64_t)(uint32_t)c.x         << 36)
                     | ((uint64_t)(uint32_t)(n1 + 1024) << 24)
                     | ((uint64_t)(uint32_t)(n2 + 1024) << 12)
                     |  (uint64_t)(uint32_t)(n3 + 1024);
        uint32_t b = (uint32_t)(key >> 31);
        uint32_t lidx = atomicAdd(&g_hist[b], 1u);
        if (lidx < CAP) {
            ulonglong2 pr; pr.x = key; pr.y = (uint64_t)(uint32_t)iB;
            g_bpairs[(size_t)b * CAP + lidx] = pr;
        }
    }
}

// ---------------------------------------------------------------------------
// Kernel 2: fused rank + scan + map. Block = 8 warps x 8 buckets each = 64
// buckets/tile -> 1024 tiles (shallow lookback chain).
// Phase 1: per-bucket flags + lrank (written to slab) + uniq counts.
// Phase 2: block scan + decoupled lookback -> global base.
// Phase 3: per-bucket map (slab re-read hits L2): inv + out_coords.
// ---------------------------------------------------------------------------
__global__ void __launch_bounds__(WPB * 32)
rankmap_kernel(float* __restrict__ out, int n)
{
    __shared__ uint64_t sk[WPB][CAP];
    __shared__ uint32_t s_uniq[WPB];        // per-warp totals
    __shared__ uint32_t s_wbase[WPB];       // per-warp global bases
    __shared__ uint16_t s_bu[WPB][BPW];     // per-bucket uniq
    __shared__ uint16_t s_bc[WPB][BPW];     // per-bucket cnt

    int warp = threadIdx.x >> 5;
    int lane = threadIdx.x & 31;
    int bid = blockIdx.x;
    int b0 = (bid * WPB + warp) * BPW;

    uint64_t* k = sk[warp];
    uint32_t warp_total = 0;

    // ---- phase 1: per-bucket flags + local ranks + uniq ----
    for (int bk = 0; bk < BPW; bk++) {
        int b = b0 + bk;
        uint32_t raw = g_hist[b];
        int cnt = (int)(raw < CAP ? raw : CAP);
        if (lane == 0) {
            g_hist[b] = 0u;                 // reset for next graph replay
            s_bc[warp][bk] = (uint16_t)cnt;
        }
        uint32_t u = 0;
        if (cnt > 0) {
            size_t start = (size_t)b * CAP;
            for (int p = lane; p < cnt; p += 32) k[p] = g_bpairs[start + p].x;
            __syncwarp();
            // first-occurrence flags -> bit 63
            for (int p = lane; p < cnt; p += 32) {
                uint64_t key = k[p];
                bool first = true;
                for (int j = 0; j < p; j++)
                    if ((k[j] & KEYMASK) == key) { first = false; break; }
                u += first ? 1u : 0u;
                if (first) k[p] = key | FIRSTBIT;
            }
            __syncwarp();
            // local rank among distinct; write back to slab (.x only)
            for (int p = lane; p < cnt; p += 32) {
                uint64_t kp = k[p];
                uint64_t myk = kp & KEYMASK;
                uint32_t less = 0;
                for (int j = 0; j < cnt; j++) {
                    uint64_t kj = k[j];
                    less += (uint32_t)(((kj & KEYMASK) < myk) & (kj >> 63));
                }
                g_bpairs[start + p].x =
                    (kp & (FIRSTBIT | KEYMASK)) | ((uint64_t)less << 47);
            }
#pragma unroll
            for (int d = 16; d > 0; d >>= 1)
                u += __shfl_xor_sync(0xFFFFFFFFu, u, d);
            __syncwarp();
        }
        if (lane == 0) s_bu[warp][bk] = (uint16_t)u;
        warp_total += u;
    }
    if (lane == 0) s_uniq[warp] = warp_total;
    __syncthreads();

    // ---- phase 2: warp 0 does block scan + decoupled lookback ----
    if (warp == 0) {
        uint32_t mine = (lane < WPB) ? s_uniq[lane] : 0u;
        uint32_t pre = mine;
#pragma unroll
        for (int d = 1; d < WPB; d <<= 1) {
            uint32_t t = __shfl_up_sync(0xFFFFFFFFu, pre, d);
            if (lane >= d) pre += t;
        }
        uint32_t agg = __shfl_sync(0xFFFFFFFFu, pre, WPB - 1);

        if (lane == 0) {
            unsigned long long packed = bid == 0
                ? (((unsigned long long)agg << 2) | 2ull)
                : (((unsigned long long)agg << 2) | 1ull);
            atomicExch(&g_tilestate[bid], packed);
        }

        uint32_t excl = 0;
        if (bid > 0) {
            int hib = bid;                      // window is [hib-32, hib)
            while (true) {
                int j = hib - 32 + (int)lane;
                unsigned long long st = 0ull;
                bool valid = (j >= 0);
                if (valid)
                    st = *((volatile unsigned long long*)&g_tilestate[j]);
                uint32_t flag = (uint32_t)(st & 3ull);
                unsigned inc = __ballot_sync(0xFFFFFFFFu, valid && flag == 2u);
                unsigned zer = __ballot_sync(0xFFFFFFFFu, valid && flag == 0u);
                if (inc) {
                    int hi = 31 - __clz(inc);
                    unsigned above = (hi == 31) ? 0u : (~0u << (hi + 1));
                    if (zer & above) continue;      // unready above; retry
                    uint32_t val = (valid && lane >= (uint32_t)hi)
                                 ? (uint32_t)(st >> 2) : 0u;
#pragma unroll
                    for (int d = 16; d > 0; d >>= 1)
                        val += __shfl_xor_sync(0xFFFFFFFFu, val, d);
                    excl += val;
                    break;
                } else {
                    if (zer) continue;              // retry window
                    uint32_t val = valid ? (uint32_t)(st >> 2) : 0u;
#pragma unroll
                    for (int d = 16; d > 0; d >>= 1)
                        val += __shfl_xor_sync(0xFFFFFFFFu, val, d);
                    excl += val;
                    hib -= 32;                      // move window down
                }
            }
            if (lane == 0)
                atomicExch(&g_tilestate[bid],
                           ((unsigned long long)(excl + agg) << 2) | 2ull);
        }

        if (lane < WPB) s_wbase[lane] = excl + pre - mine;
    }
    __syncthreads();

    // ---- phase 3: map (slab re-read hits L2) ----
    uint32_t base = s_wbase[warp];
    for (int bk = 0; bk < BPW; bk++) {
        int b = b0 + bk;
        int cnt = (int)s_bc[warp][bk];
        if (cnt > 0) {
            size_t start = (size_t)b * CAP;
            for (int p = lane; p < cnt; p += 32) {
                ulonglong2 pr = g_bpairs[start + p];
                uint64_t kp = pr.x;
                uint32_t r = base + (uint32_t)((kp >> 47) & 0xFFu);
                uint32_t orig = (uint32_t)pr.y;

                // inv map (float32) at offset 7n
                out[(size_t)7 * n + orig] = (float)r;

                if (kp & FIRSTBIT) {
                    // equal keys => identical new_coords; mean == coords
                    float cx = (float)(int)((kp >> 36) & 0x7FFu);
                    float c1 = (float)((int)((kp >> 24) & 0xFFFu) - 1024);
                    float c2 = (float)((int)((kp >> 12) & 0xFFFu) - 1024);
                    float c3 = (float)((int)( kp        & 0xFFFu) - 1024);
                    reinterpret_cast<float4*>(out + (size_t)3 * n)[r] =
                        make_float4(cx, c1, c2, c3);
                }
            }
        }
        base += (uint32_t)s_bu[warp][bk];
    }
}

// ---------------------------------------------------------------------------
// Host launch — TWO kernels total
// ---------------------------------------------------------------------------
extern "C" void kernel_launch(void* const* d_in, const int* in_sizes, int n_in,
                              void* d_out, int out_size)
{
    const float* feats  = (const float*)d_in[0];
    const int*   coords = (const int*)d_in[1];
    const int*   mask   = (const int*)d_in[2];
    const float* W1 = (const float*)d_in[3];
    const float* b1 = (const float*)d_in[4];
    const float* W2 = (const float*)d_in[5];
    const float* b2 = (const float*)d_in[6];
    const float* W3 = (const float*)d_in[7];
    const float* b3 = (const float*)d_in[8];
    float* out = (float*)d_out;

    int n = in_sizes[0] / 64;
    if (n > NMAX) n = NMAX;

    const int BLK = 256;
    int nhalf = (n + 1) >> 1;
    int gridD = (nhalf + BLK - 1) / BLK;

    // 1) decode (2 pts/thread) + keys + slab write + zero tail + state reset
    decode_kernel<<<gridD, BLK>>>(feats, coords, mask, W1, b1, W2, b2, W3, b3, out, n);

    // 2) fused rank + single-pass scan + map (1024 tiles)
    rankmap_kernel<<<NT2, WPB * 32>>>(out, n);
}

// round 14
// speedup vs baseline: 1.3935x; 1.2732x over previous
#include <cuda_runtime.h>
#include <cuda_bf16.h>
#include <cub/cub.cuh>
#include <cstdint>

#define NMAX 1000000
#define NBUCKETS 65536            // key bits 31..46
#define CAP 128                   // slab capacity (lambda ~15; >>10 sigma safe)
#define WPB 8                     // warps per block in bucket kernels

// ---------------------------------------------------------------------------
// Static device scratch (no allocations allowed anywhere)
// ---------------------------------------------------------------------------
__device__ ulonglong2 g_bpairs[(size_t)NBUCKETS * CAP]; // slab: {key(+lrank+first), idx}
__device__ uint32_t   g_hist[NBUCKETS];  // zero-init; reset by rank each call
__device__ uint32_t   g_cnt[NBUCKETS];   // bucket sizes (written by rank)
__device__ uint32_t   g_uniq[NBUCKETS];
__device__ uint32_t   g_ubase[NBUCKETS];
__device__ unsigned char g_temp[4u * 1024u * 1024u];

#define KEYMASK ((1ull << 47) - 1ull)
#define FIRSTBIT (1ull << 63)

// ---------------------------------------------------------------------------
// Packed f32x2 helpers (FFMA2 — PTX-only on sm_103a)
// ---------------------------------------------------------------------------
__device__ __forceinline__ void fma2(uint64_t& d, uint64_t a, uint64_t b, uint64_t c) {
    asm("fma.rn.f32x2 %0, %1, %2, %3;" : "=l"(d) : "l"(a), "l"(b), "l"(c));
}
__device__ __forceinline__ uint64_t dup2(float x) {
    uint64_t r; uint32_t u = __float_as_uint(x);
    asm("mov.b64 %0, {%1, %1};" : "=l"(r) : "r"(u));
    return r;
}
__device__ __forceinline__ uint64_t pack2(float lo, float hi) {
    uint64_t r;
    asm("mov.b64 %0, {%1, %2};" : "=l"(r) : "r"(__float_as_uint(lo)), "r"(__float_as_uint(hi)));
    return r;
}
__device__ __forceinline__ void unpack2(uint64_t v, float& lo, float& hi) {
    uint32_t a, b;
    asm("mov.b64 {%0, %1}, %2;" : "=r"(a), "=r"(b) : "l"(v));
    lo = __uint_as_float(a); hi = __uint_as_float(b);
}

// ---------------------------------------------------------------------------
// Kernel 1: MLP decode, TWO points per thread (i and i + n/2).
// coords/mask loaded BEFORE the MLP (latency hidden under FMA work).
// Epilogue: both keys -> both atomics -> both slab stores (overlapped).
// ---------------------------------------------------------------------------
__global__ void __launch_bounds__(256)
decode_kernel(const float* __restrict__ feats,
              const int*   __restrict__ coords,
              const int*   __restrict__ mask,
              const float* __restrict__ W1, const float* __restrict__ b1,
              const float* __restrict__ W2, const float* __restrict__ b2,
              const float* __restrict__ W3, const float* __restrict__ b3,
              float* __restrict__ out, int n)
{
    __shared__ __align__(16) float sW1[64 * 32];
    __shared__ __align__(16) float sW2[32 * 16];
    __shared__ __align__(16) float sW3[16 * 3];
    __shared__ __align__(16) float sb1[32];
    __shared__ __align__(16) float sb2[16];
    __shared__ __align__(16) float sb3[4];

    for (int t = threadIdx.x; t < 64 * 32; t += blockDim.x) sW1[t] = W1[t];
    for (int t = threadIdx.x; t < 32 * 16; t += blockDim.x) sW2[t] = W2[t];
    for (int t = threadIdx.x; t < 16 * 3;  t += blockDim.x) sW3[t] = W3[t];
    if (threadIdx.x < 32) sb1[threadIdx.x] = b1[threadIdx.x];
    if (threadIdx.x < 16) sb2[threadIdx.x] = b2[threadIdx.x];
    if (threadIdx.x < 3)  sb3[threadIdx.x] = b3[threadIdx.x];
    __syncthreads();

    int nhalf = (n + 1) >> 1;
    int i = blockIdx.x * blockDim.x + threadIdx.x;
    if (i >= nhalf) return;
    int iA = i;
    int iB = i + nhalf;
    bool hasB = (iB < n);
    int iBs = hasB ? iB : iA;            // safe source for B-lane loads

    // ---- EARLY loads: coords + mask (latency hidden under the MLP) ----
    int4 cA = reinterpret_cast<const int4*>(coords)[iA];
    int4 cB = reinterpret_cast<const int4*>(coords)[iBs];
    int mAi = mask[iA];
    int mBi = mask[iBs];

    // ---- layer 1: 64 -> 32, two points, shared weight loads ----
    uint64_t accA[16], accB[16];
#pragma unroll
    for (int p = 0; p < 16; p++) {
        uint64_t b = pack2(sb1[2 * p], sb1[2 * p + 1]);
        accA[p] = b; accB[p] = b;
    }

    const ulonglong2* w1q = reinterpret_cast<const ulonglong2*>(sW1); // [64][8]
    const float4* fA = reinterpret_cast<const float4*>(feats) + (size_t)iA * 16;
    const float4* fB = reinterpret_cast<const float4*>(feats) + (size_t)iBs * 16;
#pragma unroll
    for (int k4 = 0; k4 < 16; k4++) {
        float4 fa = fA[k4];
        float4 fb = fB[k4];
        uint64_t a0 = dup2(fa.x), a1 = dup2(fa.y), a2 = dup2(fa.z), a3 = dup2(fa.w);
        uint64_t e0 = dup2(fb.x), e1 = dup2(fb.y), e2 = dup2(fb.z), e3 = dup2(fb.w);
        const ulonglong2* r0 = &w1q[(k4 * 4 + 0) * 8];
        const ulonglong2* r1 = &w1q[(k4 * 4 + 1) * 8];
        const ulonglong2* r2 = &w1q[(k4 * 4 + 2) * 8];
        const ulonglong2* r3 = &w1q[(k4 * 4 + 3) * 8];
#pragma unroll
        for (int q = 0; q < 8; q++) {
            ulonglong2 w;
            w = r0[q];
            fma2(accA[2*q], a0, w.x, accA[2*q]); fma2(accA[2*q+1], a0, w.y, accA[2*q+1]);
            fma2(accB[2*q], e0, w.x, accB[2*q]); fma2(accB[2*q+1], e0, w.y, accB[2*q+1]);
            w = r1[q];
            fma2(accA[2*q], a1, w.x, accA[2*q]); fma2(accA[2*q+1], a1, w.y, accA[2*q+1]);
            fma2(accB[2*q], e1, w.x, accB[2*q]); fma2(accB[2*q+1], e1, w.y, accB[2*q+1]);
            w = r2[q];
            fma2(accA[2*q], a2, w.x, accA[2*q]); fma2(accA[2*q+1], a2, w.y, accA[2*q+1]);
            fma2(accB[2*q], e2, w.x, accB[2*q]); fma2(accB[2*q+1], e2, w.y, accB[2*q+1]);
            w = r3[q];
            fma2(accA[2*q], a3, w.x, accA[2*q]); fma2(accA[2*q+1], a3, w.y, accA[2*q+1]);
            fma2(accB[2*q], e3, w.x, accB[2*q]); fma2(accB[2*q+1], e3, w.y, accB[2*q+1]);
        }
    }

    float h1A[32], h1B[32];
#pragma unroll
    for (int p = 0; p < 16; p++) {
        float lo, hi;
        unpack2(accA[p], lo, hi);
        h1A[2*p] = fmaxf(lo, 0.0f); h1A[2*p+1] = fmaxf(hi, 0.0f);
        unpack2(accB[p], lo, hi);
        h1B[2*p] = fmaxf(lo, 0.0f); h1B[2*p+1] = fmaxf(hi, 0.0f);
    }

    // ---- layer 2: 32 -> 16, two points, shared weight loads ----
    uint64_t ac2A[8], ac2B[8];
#pragma unroll
    for (int p = 0; p < 8; p++) {
        uint64_t b = pack2(sb2[2 * p], sb2[2 * p + 1]);
        ac2A[p] = b; ac2B[p] = b;
    }
    const ulonglong2* w2q = reinterpret_cast<const ulonglong2*>(sW2); // [32][4]
#pragma unroll
    for (int k = 0; k < 32; k++) {
        uint64_t a = dup2(h1A[k]);
        uint64_t e = dup2(h1B[k]);
        const ulonglong2* wr = &w2q[k * 4];
#pragma unroll
        for (int q = 0; q < 4; q++) {
            ulonglong2 w = wr[q];
            fma2(ac2A[2*q],   a, w.x, ac2A[2*q]);   fma2(ac2A[2*q+1], a, w.y, ac2A[2*q+1]);
            fma2(ac2B[2*q],   e, w.x, ac2B[2*q]);   fma2(ac2B[2*q+1], e, w.y, ac2B[2*q+1]);
        }
    }

    float h2A[16], h2B[16];
#pragma unroll
    for (int p = 0; p < 8; p++) {
        float lo, hi;
        unpack2(ac2A[p], lo, hi);
        h2A[2*p] = fmaxf(lo, 0.0f); h2A[2*p+1] = fmaxf(hi, 0.0f);
        unpack2(ac2B[p], lo, hi);
        h2B[2*p] = fmaxf(lo, 0.0f); h2B[2*p+1] = fmaxf(hi, 0.0f);
    }

    // ---- layer 3: 16 -> 3, two points ----
    float oA0 = sb3[0], oA1 = sb3[1], oA2 = sb3[2];
    float oB0 = sb3[0], oB1 = sb3[1], oB2 = sb3[2];
#pragma unroll
    for (int k = 0; k < 16; k++) {
        float w0 = sW3[k * 3 + 0], w1 = sW3[k * 3 + 1], w2 = sW3[k * 3 + 2];
        oA0 = fmaf(h2A[k], w0, oA0); oA1 = fmaf(h2A[k], w1, oA1); oA2 = fmaf(h2A[k], w2, oA2);
        oB0 = fmaf(h2B[k], w0, oB0); oB1 = fmaf(h2B[k], w1, oB1); oB2 = fmaf(h2B[k], w2, oB2);
    }

    // ---- epilogue: both keys, both atomics, then both stores ----
    float mA = (mAi != 0) ? 1.0f : 0.0f;
    float mB = (mBi != 0) ? 1.0f : 0.0f;
    oA0 *= mA; oA1 *= mA; oA2 *= mA;
    oB0 *= mB; oB1 *= mB; oB2 *= mB;

    out[(size_t)3 * iA + 0] = oA0;
    out[(size_t)3 * iA + 1] = oA1;
    out[(size_t)3 * iA + 2] = oA2;
    if (hasB) {
        out[(size_t)3 * iB + 0] = oB0;
        out[(size_t)3 * iB + 1] = oB1;
        out[(size_t)3 * iB + 2] = oB2;
    }

    int a1i = cA.y + (int)rintf(oA0);
    int a2i = cA.z + (int)rintf(oA1);
    int a3i = cA.w + (int)rintf(oA2);
    uint64_t keyA = ((uint64_t)(uint32_t)cA.x          << 36)
                  | ((uint64_t)(uint32_t)(a1i + 1024)  << 24)
                  | ((uint64_t)(uint32_t)(a2i + 1024)  << 12)
                  |  (uint64_t)(uint32_t)(a3i + 1024);
    uint32_t bA = (uint32_t)(keyA >> 31);

    uint64_t keyB = 0; uint32_t bB = 0;
    if (hasB) {
        int b1i = cB.y + (int)rintf(oB0);
        int b2i = cB.z + (int)rintf(oB1);
        int b3i = cB.w + (int)rintf(oB2);
        keyB = ((uint64_t)(uint32_t)cB.x          << 36)
             | ((uint64_t)(uint32_t)(b1i + 1024)  << 24)
             | ((uint64_t)(uint32_t)(b2i + 1024)  << 12)
             |  (uint64_t)(uint32_t)(b3i + 1024);
        bB = (uint32_t)(keyB >> 31);
    }

    // overlap both atomics before consuming either result
    uint32_t lA = atomicAdd(&g_hist[bA], 1u);
    uint32_t lB = hasB ? atomicAdd(&g_hist[bB], 1u) : 0u;

    if (lA < CAP) {
        ulonglong2 pr; pr.x = keyA; pr.y = (uint64_t)(uint32_t)iA;
        g_bpairs[(size_t)bA * CAP + lA] = pr;
    }
    if (hasB && lB < CAP) {
        ulonglong2 pr; pr.x = keyB; pr.y = (uint64_t)(uint32_t)iB;
        g_bpairs[(size_t)bB * CAP + lB] = pr;
    }
}

// ---------------------------------------------------------------------------
// Kernel 2: per-bucket (one warp each): first-occurrence flags, local rank
// among distinct keys, unique count. Also: cnt -> g_cnt, hist reset.
// ---------------------------------------------------------------------------
__global__ void __launch_bounds__(WPB * 32)
rank_kernel(void)
{
    __shared__ uint64_t sk[WPB][CAP];   // bit63 = first flag after pass 1

    int warp = threadIdx.x >> 5;
    int lane = threadIdx.x & 31;
    int b = blockIdx.x * WPB + warp;

    uint32_t raw = g_hist[b];
    int cnt = (int)(raw < CAP ? raw : CAP);
    if (lane == 0) {
        g_cnt[b] = (uint32_t)cnt;
        g_hist[b] = 0u;                 // reset for next graph replay
        if (cnt == 0) g_uniq[b] = 0;
    }
    if (cnt == 0) return;

    size_t start = (size_t)b * CAP;
    uint64_t* k = sk[warp];
    for (int p = lane; p < cnt; p += 32) k[p] = g_bpairs[start + p].x;
    __syncwarp();

    // pass 1: first-occurrence flags -> bit 63 in smem
    uint32_t u = 0;
    for (int p = lane; p < cnt; p += 32) {
        uint64_t key = k[p];
        bool first = true;
        for (int j = 0; j < p; j++)
            if ((k[j] & KEYMASK) == key) { first = false; break; }
        u += first ? 1u : 0u;
        if (first) k[p] = key | FIRSTBIT;   // lanes own disjoint p: no race
    }
    __syncwarp();

    // pass 2: local rank among distinct (count firsts with smaller key)
    for (int p = lane; p < cnt; p += 32) {
        uint64_t kp = k[p];
        uint64_t myk = kp & KEYMASK;
        uint32_t less = 0;
        for (int j = 0; j < cnt; j++) {
            uint64_t kj = k[j];
            less += (uint32_t)(((kj & KEYMASK) < myk) & (kj >> 63));
        }
        g_bpairs[start + p].x =
            (kp & (FIRSTBIT | KEYMASK)) | ((uint64_t)less << 47);
    }

#pragma unroll
    for (int d = 16; d > 0; d >>= 1)
        u += __shfl_down_sync(0xFFFFFFFFu, u, d);
    if (lane == 0) g_uniq[b] = u;
}

// ---------------------------------------------------------------------------
// Kernel 3: warp-per-bucket map: inv = ubase + lrank; firsts write out_coords
// decoded from the key. Thread-indexed tail zeroing for rows >= total_uniq.
// ---------------------------------------------------------------------------
__global__ void __launch_bounds__(WPB * 32)
map_kernel(float* __restrict__ out, int n)
{
    uint32_t total = g_ubase[NBUCKETS - 1] + g_uniq[NBUCKETS - 1];

    // tail zeroing by global thread id
    int t = blockIdx.x * blockDim.x + threadIdx.x;
    if (t < n && (uint32_t)t >= total)
        reinterpret_cast<float4*>(out + (size_t)3 * n)[t] =
            make_float4(0.f, 0.f, 0.f, 0.f);

    int warp = threadIdx.x >> 5;
    int lane = threadIdx.x & 31;
    int b = blockIdx.x * WPB + warp;

    int cnt = (int)g_cnt[b];
    if (cnt == 0) return;
    size_t start = (size_t)b * CAP;
    uint32_t base = g_ubase[b];

    for (int p = lane; p < cnt; p += 32) {
        ulonglong2 pr = g_bpairs[start + p];
        uint64_t kp = pr.x;
        uint32_t r = base + (uint32_t)((kp >> 47) & 0xFFu);
        uint32_t orig = (uint32_t)pr.y;

        // inv map (float32) at offset 7n
        out[(size_t)7 * n + orig] = (float)r;

        if (kp & FIRSTBIT) {
            // equal keys => identical new_coords; mean == the coords
            float cx = (float)(int)((kp >> 36) & 0x7FFu);
            float c1 = (float)((int)((kp >> 24) & 0xFFFu) - 1024);
            float c2 = (float)((int)((kp >> 12) & 0xFFFu) - 1024);
            float c3 = (float)((int)( kp        & 0xFFFu) - 1024);
            reinterpret_cast<float4*>(out + (size_t)3 * n)[r] =
                make_float4(cx, c1, c2, c3);
        }
    }
}

// ---------------------------------------------------------------------------
// Host launch
// ---------------------------------------------------------------------------
extern "C" void kernel_launch(void* const* d_in, const int* in_sizes, int n_in,
                              void* d_out, int out_size)
{
    const float* feats  = (const float*)d_in[0];
    const int*   coords = (const int*)d_in[1];
    const int*   mask   = (const int*)d_in[2];
    const float* W1 = (const float*)d_in[3];
    const float* b1 = (const float*)d_in[4];
    const float* W2 = (const float*)d_in[5];
    const float* b2 = (const float*)d_in[6];
    const float* W3 = (const float*)d_in[7];
    const float* b3 = (const float*)d_in[8];
    float* out = (float*)d_out;

    int n = in_sizes[0] / 64;
    if (n > NMAX) n = NMAX;

    void *p_uniq, *p_ubase, *p_temp;
    cudaGetSymbolAddress(&p_uniq,  g_uniq);
    cudaGetSymbolAddress(&p_ubase, g_ubase);
    cudaGetSymbolAddress(&p_temp,  g_temp);

    const int BLK = 256;
    int nhalf = (n + 1) >> 1;
    int gridD = (nhalf + BLK - 1) / BLK;

    // 1) decode (2 pts/thread) + keys + direct slab write
    decode_kernel<<<gridD, BLK>>>(feats, coords, mask, W1, b1, W2, b2, W3, b3, out, n);

    // 2) per-bucket flags + local ranks + unique counts (1 warp / bucket)
    rank_kernel<<<NBUCKETS / WPB, WPB * 32>>>();

    // 3) exclusive scan of unique counts -> global rank bases
    size_t tb = 0;
    cub::DeviceScan::ExclusiveSum(nullptr, tb, (const uint32_t*)p_uniq,
                                  (uint32_t*)p_ubase, NBUCKETS, (cudaStream_t)0);
    if (tb > 4u * 1024u * 1024u) return;
    cub::DeviceScan::ExclusiveSum(p_temp, tb, (const uint32_t*)p_uniq,
                                  (uint32_t*)p_ubase, NBUCKETS, (cudaStream_t)0);

    // 4) warp-per-bucket map: inv + out_coords + tail zeroing
    map_kernel<<<NBUCKETS / WPB, WPB * 32>>>(out, n);
}